// round 16
// baseline (speedup 1.0000x reference)
#include <cuda_runtime.h>
#include <cuda_fp16.h>
#include <math.h>
#include <stdint.h>

#define NPIX 192
#define MPTS 36864
#define NN   36864
#define ZSP  48            // adj split-K CTAs per P-variant (3*48 = 144 CTAs)
#define TWO_PI_F 6.28318530717958647693f
#define ESCALE 4096.0f
#define EUNSC  (1.0f/4096.0f)

typedef unsigned short u16;
typedef unsigned int   u32;
typedef unsigned long long u64;

// ---------------- device globals ----------------
// op A (trig, m-major, u16/k, PRMT-expanded at stage): P1=c, P2=s, P3=c+s
static __device__ __align__(16) u16 g_opAc [(size_t)MPTS*NPIX];
static __device__ __align__(16) u16 g_opAs [(size_t)MPTS*NPIX];
static __device__ __align__(16) u16 g_opAcs[(size_t)MPTS*NPIX];
// adj B (trig, y-major, u16/k): same three variants
static __device__ __align__(16) u16 g_adjBc [(size_t)NPIX*MPTS];
static __device__ __align__(16) u16 g_adjBs [(size_t)NPIX*MPTS];
static __device__ __align__(16) u16 g_adjBcs[(size_t)NPIX*MPTS];
// op B (image splits, u32 {h,l}/k, direct stage): P1=ir, P2=ii, P3=ir+ii
static __device__ __align__(16) u32 g_opB1[(size_t)NPIX*NPIX];
static __device__ __align__(16) u32 g_opB2[(size_t)NPIX*NPIX];
static __device__ __align__(16) u32 g_opB3[(size_t)NPIX*NPIX];
// adj A (E splits, u32 {h,l}/k): P1=er, P2=ei, P3=ei-er   (ESCALE applied)
static __device__ __align__(16) u32 g_E1[(size_t)NPIX*MPTS];
static __device__ __align__(16) u32 g_E2[(size_t)NPIX*MPTS];
static __device__ __align__(16) u32 g_E3[(size_t)NPIX*MPTS];
static __device__ u32 g_Am[(size_t)MPTS*NPIX];   // packed (ar,ai) fp16 [m][x]
static __device__ u32 g_Ax[(size_t)NPIX*MPTS];   // packed (ar,ai) fp16 [x][m]
static __device__ float g_part[(size_t)3*ZSP*NN];  // 21MB  [p][z][x][y]
static __device__ float g_uv[6][MPTS];             // [2p+sel]
static __device__ float g_w[MPTS], g_dre[MPTS], g_dim[MPTS];

// ---------------- helpers ----------------
__device__ __forceinline__ u32 s2u(const void* p){u32 a;asm("{ .reg .u64 t; cvta.to.shared.u64 t, %1; cvt.u32.u64 %0, t; }":"=r"(a):"l"(p));return a;}
__device__ __forceinline__ u16 h16(float v){ __half h=__float2half_rn(v); return __half_as_ushort(h); }
__device__ __forceinline__ u32 splitu(float v){
    __half a=__float2half_rn(v);
    __half b=__float2half_rn(v-__half2float(a));
    return (u32)__half_as_ushort(a) | ((u32)__half_as_ushort(b)<<16);
}
__device__ __forceinline__ float2 up16(u32 v){
    __half2 h = *reinterpret_cast<__half2*>(&v);
    return __half22float2(h);
}
__device__ __forceinline__ u32 prmt(u32 v,u32 sel){u32 r;asm("prmt.b32 %0,%1,%1,%2;":"=r"(r):"r"(v),"r"(sel));return r;}
__device__ __forceinline__ void hmma(float* c,u32 a0,u32 a1,u32 a2,u32 a3,u32 b0,u32 b1){
    asm volatile("mma.sync.aligned.m16n8k16.row.col.f32.f16.f16.f32 {%0,%1,%2,%3},{%4,%5,%6,%7},{%8,%9},{%0,%1,%2,%3};"
        : "+f"(c[0]),"+f"(c[1]),"+f"(c[2]),"+f"(c[3])
        : "r"(a0),"r"(a1),"r"(a2),"r"(a3),"r"(b0),"r"(b1));
}
#define LDMX4(r0,r1,r2,r3,addr) \
    asm volatile("ldmatrix.sync.aligned.m8n8.x4.shared.b16 {%0,%1,%2,%3},[%4];" \
        : "=r"(r0),"=r"(r1),"=r"(r2),"=r"(r3) : "r"(addr))

// ---------------- staging: packed u16/k (48B -> 96B via PRMT) or raw 96B ------
__device__ __forceinline__ void stage_ld(const void* src,int packed,size_t stride,int c,int r,uint4* v){
    if(packed){
        const uint4* s = (const uint4*)((const u32*)src + (size_t)r*stride + c*12);
        v[0]=s[0]; v[1]=s[1]; v[2]=s[2];
    } else {
        const uint4* s = (const uint4*)((const u16*)src + (size_t)r*stride + c*48);
#pragma unroll
        for(int q=0;q<6;++q) v[q]=s[q];
    }
}
__device__ __forceinline__ void stage_st(char* dst,int packed,const uint4* v){
    uint4* d=(uint4*)dst;
    if(packed){
#pragma unroll
        for(int q=0;q<3;++q){
            uint4 pv=v[q], o1, o2;
            o1.x=prmt(pv.x,0x1010u); o1.y=prmt(pv.x,0x3232u);
            o1.z=prmt(pv.y,0x1010u); o1.w=prmt(pv.y,0x3232u);
            o2.x=prmt(pv.z,0x1010u); o2.y=prmt(pv.z,0x3232u);
            o2.z=prmt(pv.w,0x1010u); o2.w=prmt(pv.w,0x3232u);
            d[2*q]=o1; d[2*q+1]=o2;
        }
    } else {
#pragma unroll
        for(int q=0;q<6;++q) d[q]=v[q];
    }
}

// ---------------- GEMM core: M=192, N=192, K-chunk = 48 slots (frozen) -------
__device__ __forceinline__ void compute192(const char* sm,float* acc){
    int lane = threadIdx.x & 31, w = threadIdx.x >> 5;
    int wm = w & 3, wn = w >> 2;
    int q = lane & 7, quad = lane >> 3;
    u32 smu = s2u(sm);
    u32 aAddr0 = smu + (u32)((wm*48 + (quad&1)*8 + q)*112 + ((quad>>1)*8)*2);
    u32 bAddr0 = smu + 21504u + (u32)((wn*64 + ((quad>>1)&1)*8 + q)*112 + ((quad&1)*8)*2);
#pragma unroll
    for(int s=0;s<3;++s){
        u32 a[3][4];
#pragma unroll
        for(int mg=0;mg<3;++mg)
            LDMX4(a[mg][0],a[mg][1],a[mg][2],a[mg][3], aAddr0 + (u32)(mg*16*112 + s*32));
#pragma unroll
        for(int ng=0;ng<4;++ng){
            u32 b0,b1,b2,b3;
            LDMX4(b0,b1,b2,b3, bAddr0 + (u32)(ng*16*112 + s*32));
#pragma unroll
            for(int mg=0;mg<3;++mg){
                hmma(acc + (mg*8 + ng*2    )*4, a[mg][0],a[mg][1],a[mg][2],a[mg][3], b0,b1);
                hmma(acc + (mg*8 + ng*2 + 1)*4, a[mg][0],a[mg][1],a[mg][2],a[mg][3], b2,b3);
            }
        }
    }
}
__device__ __forceinline__ void gemm192(const void* gA,size_t sA,int pA,
                                        const void* gB,size_t sB,int pB,
                                        int nch,char* sm,float* acc){
    int t = threadIdx.x;
    int role = t >= 192;
    int r = role ? t-192 : t;
    const void* src = role ? gB : gA;
    int packed = role ? pB : pA;
    size_t stride = role ? sB : sA;
    char* dst = sm + (role?21504:0) + r*112;
    uint4 v[6];
    stage_ld(src,packed,stride,0,r,v);
    stage_st(dst,packed,v);
    __syncthreads();
    for(int c=0;c<nch;++c){
        if(c+1<nch) stage_ld(src,packed,stride,c+1,r,v);
        compute192(sm,acc);
        if(c+1<nch){
            __syncthreads();
            stage_st(dst,packed,v);
            __syncthreads();
        }
    }
}

// ---------------- builds ----------------
__global__ void k_build_ky(const float* __restrict__ traj){
    int m = blockIdx.x*256 + threadIdx.x;
    int oct = blockIdx.y;
    float ky = traj[2*m+1];
    float ph = ky*(float)(oct*8-96); float r = ph-rintf(ph);
    float s,c; __sincosf(-TWO_PI_F*r,&s,&c);
    float su,cu; __sincosf(-TWO_PI_F*ky,&su,&cu);
    for(int i=0;i<8;++i){
        int y = oct*8+i;
        u16 ch=h16(c), sh=h16(s), csh=h16(c+s);
        g_opAc [(size_t)m*NPIX+y]=ch;
        g_opAs [(size_t)m*NPIX+y]=sh;
        g_opAcs[(size_t)m*NPIX+y]=csh;
        g_adjBc [(size_t)y*MPTS+m]=ch;
        g_adjBs [(size_t)y*MPTS+m]=sh;
        g_adjBcs[(size_t)y*MPTS+m]=csh;
        float nc = c*cu - s*su; s = s*cu + c*su; c = nc;
    }
}
__global__ void k_build_kx(const float* __restrict__ traj){
    int m = blockIdx.x*256 + threadIdx.x;
    int oct = blockIdx.y;
    float kx = traj[2*m];
    float ph = kx*(float)(oct*8-96); float r = ph-rintf(ph);
    float s,c; __sincosf(-TWO_PI_F*r,&s,&c);
    float su,cu; __sincosf(-TWO_PI_F*kx,&su,&cu);
    for(int i=0;i<8;++i){
        int x = oct*8+i;
        u32 pk = (u32)h16(c) | ((u32)h16(s)<<16);
        g_Am[(size_t)m*NPIX+x]=pk; g_Ax[(size_t)x*MPTS+m]=pk;
        float nc = c*cu - s*su; s = s*cu + c*su; c = nc;
    }
}
__global__ void k_opB(const float* __restrict__ xin){
    int idx = blockIdx.x*256 + threadIdx.x;
    float re = xin[idx], im = xin[NN+idx];
    g_opB1[idx]=splitu(re); g_opB2[idx]=splitu(im); g_opB3[idx]=splitu(re+im);
}
// E builds: er,ei = ESCALE*conj(Ax)*d ; es = ei - er
__global__ void k_Ebuild(int pipe){
    int m0 = (blockIdx.x*256 + threadIdx.x)*2;
    int x = blockIdx.y;
    u64 w2 = *(const u64*)(g_Ax + (size_t)x*MPTS + m0);
    u64 o1,o2,o3;
#pragma unroll
    for(int j=0;j<2;++j){
        float2 cs = up16(j ? (u32)(w2>>32) : (u32)w2);
        int m = m0 + j;
        float er, ei;
        if(pipe){ float wv=g_w[m]*ESCALE; er = cs.x*wv; ei = -cs.y*wv; }
        else { float dr=g_dre[m]*ESCALE, di=g_dim[m]*ESCALE;
               er = cs.x*dr + cs.y*di; ei = cs.x*di - cs.y*dr; }
        u64 a=splitu(er), b=splitu(ei), d=splitu(ei-er);
        if(j==0){ o1=a; o2=b; o3=d; }
        else { o1|=a<<32; o2|=b<<32; o3|=d<<32; }
    }
    *(u64*)(g_E1 + (size_t)x*MPTS + m0) = o1;
    *(u64*)(g_E2 + (size_t)x*MPTS + m0) = o2;
    *(u64*)(g_E3 + (size_t)x*MPTS + m0) = o3;
}

// ---------------- elementwise ----------------
__global__ void k_winit(){int i=blockIdx.x*256+threadIdx.x; g_w[i]=1.0f;}
__global__ void k_scombw(){int i=blockIdx.x*256+threadIdx.x;
    float sre=g_uv[0][i]+g_uv[2][i]+g_uv[4][i];
    float sim=g_uv[1][i]+g_uv[3][i]+g_uv[5][i];
    float m=sqrtf(sre*sre+sim*sim); g_w[i]=g_w[i]/fmaxf(m,1e-20f);}
__global__ void k_scombd(){int i=blockIdx.x*256+threadIdx.x;
    float sre=g_uv[0][i]+g_uv[2][i]+g_uv[4][i];
    float sim=g_uv[1][i]+g_uv[3][i]+g_uv[5][i];
    g_dre[i]=g_w[i]*sre; g_dim[i]=g_w[i]*sim;}
// adj combine: re = S1+S2, im = S3+S1-S2
__device__ __forceinline__ float2 adj_combine(int idx){
    float s1=0.f,s2=0.f,s3=0.f;
#pragma unroll 8
    for(int z=0;z<ZSP;++z){
        s1 += g_part[((size_t)z        )*NN + idx];
        s2 += g_part[((size_t)(ZSP+z)  )*NN + idx];
        s3 += g_part[((size_t)(2*ZSP+z))*NN + idx];
    }
    return make_float2(s1+s2, s3+s1-s2);
}
__global__ void k_reduceB(){
    int idx = blockIdx.x*256 + threadIdx.x;
    float2 v = adj_combine(idx);
    g_opB1[idx]=splitu(v.x); g_opB2[idx]=splitu(v.y); g_opB3[idx]=splitu(v.x+v.y);
}
__global__ void k_reduceOut(float* __restrict__ out){
    int idx = blockIdx.x*256 + threadIdx.x;
    float2 v = adj_combine(idx);
    out[idx]=v.x; out[NN+idx]=v.y;
}

// ---------------- op GEMM: P_p[m,x] + fused A-dot partials -------------------
// P1 = sum_y c*ir, P2 = sum_y s*ii, P3 = sum_y (c+s)(ir+ii)
// s_re = (ar+ai)P1 + (ai-ar)P2 - ai*P3 ; s_im = (ai-ar)P1 - (ar+ai)P2 + ar*P3
__global__ void __launch_bounds__(384) k_opg(){
    extern __shared__ char dsm[];
    float acc[96];
#pragma unroll
    for(int i=0;i<96;++i) acc[i]=0.f;
    int p = blockIdx.x, blk = blockIdx.y;
    const u16* gA = (p==0?g_opAc:(p==1?g_opAs:g_opAcs)) + (size_t)blk*192*NPIX;
    const u32* gB = (p==0?g_opB1:(p==1?g_opB2:g_opB3));
    gemm192(gA, NPIX/2, 1, gB, NPIX*2, 0, 8, dsm, acc);

    int lane = threadIdx.x&31, w = threadIdx.x>>5;
    int wm = w & 3, wn = w >> 2;
    int g = lane>>2, j3 = lane&3;
    float u1[3][2], u2[3][2];
#pragma unroll
    for(int mg=0;mg<3;++mg){ u1[mg][0]=u1[mg][1]=0.f; u2[mg][0]=u2[mg][1]=0.f; }
#pragma unroll
    for(int mg=0;mg<3;++mg){
        int m0 = blk*192 + wm*48 + mg*16 + g;
#pragma unroll
        for(int tp=0;tp<8;++tp){
            int x = wn*64 + tp*8 + 2*j3;
            const float* c = acc + (mg*8+tp)*4;
#pragma unroll
            for(int h=0;h<2;++h){
                u64 w0 = __ldg((const u64*)(g_Am + (size_t)(m0+8*h)*NPIX + x));
#pragma unroll
                for(int q=0;q<2;++q){
                    float2 cs = up16(q ? (u32)(w0>>32) : (u32)w0);
                    float ar=cs.x, ai=cs.y, cr, ci;
                    if(p==0){ cr=ar+ai; ci=ai-ar; }
                    else if(p==1){ cr=ai-ar; ci=-(ar+ai); }
                    else { cr=-ai; ci=ar; }
                    float pv = c[2*h+q];
                    u1[mg][h] += cr*pv;
                    u2[mg][h] += ci*pv;
                }
            }
        }
    }
#pragma unroll
    for(int o=1;o<4;o<<=1){
#pragma unroll
        for(int mg=0;mg<3;++mg){
            u1[mg][0]+=__shfl_xor_sync(0xffffffffu,u1[mg][0],o);
            u1[mg][1]+=__shfl_xor_sync(0xffffffffu,u1[mg][1],o);
            u2[mg][0]+=__shfl_xor_sync(0xffffffffu,u2[mg][0],o);
            u2[mg][1]+=__shfl_xor_sync(0xffffffffu,u2[mg][1],o);
        }
    }
    __syncthreads();
    float* sr = (float*)dsm;
    if(j3==0){
#pragma unroll
        for(int mg=0;mg<3;++mg){
#pragma unroll
            for(int h=0;h<2;++h){
                int row = h*8 + g;
                int off = (((wn*4 + wm)*3 + mg)*16 + row)*2;
                sr[off]   = u1[mg][h];
                sr[off+1] = u2[mg][h];
            }
        }
    }
    __syncthreads();
    int t = threadIdx.x;
    int row192 = t >> 1, sel = t & 1;
    int twm = row192/48, rem = row192 - twm*48;
    int tmg = rem >> 4, trow = rem & 15;
    float s = 0.f;
#pragma unroll
    for(int qn=0;qn<3;++qn)
        s += sr[(((qn*4 + twm)*3 + tmg)*16 + trow)*2 + sel];
    g_uv[2*p + sel][blk*192 + row192] = s;
}

// ---------------- adj GEMM: P_p split-K partials ------------------------------
// P1 = sum_m er*c, P2 = sum_m ei*s, P3 = sum_m (ei-er)(c+s)
__global__ void __launch_bounds__(384) k_adjg(){
    extern __shared__ char dsm[];
    float acc[96];
#pragma unroll
    for(int i=0;i<96;++i) acc[i]=0.f;
    int p = blockIdx.x, z = blockIdx.y;
    const u32* gA = (p==0?g_E1:(p==1?g_E2:g_E3));
    const u16* gBp = (p==0?g_adjBc:(p==1?g_adjBs:g_adjBcs));
    const void* gAv = (const u16*)gA + (size_t)z*1536;      // 768 m per z
    const void* gBv = (const u32*)gBp + (size_t)z*384;
    gemm192(gAv, MPTS*2, 0, gBv, MPTS/2, 1, 32, dsm, acc);

    int lane = threadIdx.x&31, w = threadIdx.x>>5;
    int wm = w & 3, wn = w >> 2;
    int g = lane>>2, j3 = lane&3;
    float* pp = g_part + ((size_t)p*ZSP + z)*NN;
#pragma unroll
    for(int mg=0;mg<3;++mg){
        int x0 = wm*48 + mg*16 + g;
#pragma unroll
        for(int tp=0;tp<8;++tp){
            int y = wn*64 + tp*8 + 2*j3;
            const float* c = acc + (mg*8+tp)*4;
            *(float2*)&pp[(size_t)x0*192+y]     = make_float2(c[0]*EUNSC,c[1]*EUNSC);
            *(float2*)&pp[(size_t)(x0+8)*192+y] = make_float2(c[2]*EUNSC,c[3]*EUNSC);
        }
    }
}

// ---------------- driver ----------------
extern "C" void kernel_launch(void* const* d_in, const int* in_sizes, int n_in,
                              void* d_out, int out_size) {
    const float* xin  = (const float*)d_in[0];
    const float* traj = (const float*)d_in[1];
    float* out = (float*)d_out;
    const int SMEM = 43008;

    dim3 gb(144,24);
    k_build_ky<<<gb,256>>>(traj);
    k_build_kx<<<gb,256>>>(traj);
    k_winit<<<144,256>>>();

    for(int it=0; it<3; ++it){
        k_Ebuild<<<dim3(72,192),256>>>(1);
        k_adjg<<<dim3(3,ZSP),384,SMEM>>>();
        k_reduceB<<<144,256>>>();
        k_opg<<<dim3(3,192),384,SMEM>>>();
        k_scombw<<<144,256>>>();
    }
    k_opB<<<144,256>>>(xin);
    k_opg<<<dim3(3,192),384,SMEM>>>();
    k_scombd<<<144,256>>>();
    k_Ebuild<<<dim3(72,192),256>>>(0);
    k_adjg<<<dim3(3,ZSP),384,SMEM>>>();
    k_reduceOut<<<144,256>>>(out);
}

// round 17
// speedup vs baseline: 1.0463x; 1.0463x over previous
#include <cuda_runtime.h>
#include <cuda_fp16.h>
#include <math.h>
#include <stdint.h>

#define NPIX 192
#define MPTS 36864
#define NN   36864
#define KOP  768           // 192*4 slots
#define ZS   64
#define TWO_PI_F 6.28318530717958647693f
#define ESCALE 4096.0f
#define EUNSC  (1.0f/4096.0f)

typedef unsigned short u16;
typedef unsigned int   u32;
typedef unsigned long long u64;

// ---------------- device globals ----------------
static __device__ __align__(16) u32 g_opAp[(size_t)MPTS*NPIX];     // packed {c,s} [m][y]
static __device__ __align__(16) u32 g_adjBp[(size_t)NPIX*MPTS];    // packed {c,s} [y][m]
static __device__ __align__(16) u16 g_opBr[(size_t)NPIX*KOP];
static __device__ __align__(16) u16 g_opBi[(size_t)NPIX*KOP];
static __device__ u32 g_Am[(size_t)MPTS*NPIX];                     // packed (c,s) [m][x]
static __device__ __align__(16) u32 g_Ax[(size_t)NPIX*MPTS];       // packed (c,s) [x][m]
static __device__ __align__(16) float2 g_d[MPTS];                  // ESCALE-scaled adj input
static __device__ float g_part[(size_t)2*ZS*NN];
static __device__ float g_uv[4][MPTS];
static __device__ float g_w[MPTS];

// ---------------- helpers ----------------
__device__ __forceinline__ u32 s2u(const void* p){u32 a;asm("{ .reg .u64 t; cvta.to.shared.u64 t, %1; cvt.u32.u64 %0, t; }":"=r"(a):"l"(p));return a;}
__device__ __forceinline__ u16 h16(float v){ __half h=__float2half_rn(v); return __half_as_ushort(h); }
__device__ __forceinline__ u32 splitu(float v){
    __half a=__float2half_rn(v);
    __half b=__float2half_rn(v-__half2float(a));
    return (u32)__half_as_ushort(a) | ((u32)__half_as_ushort(b)<<16);
}
__device__ __forceinline__ float2 up16(u32 v){
    __half2 h = *reinterpret_cast<__half2*>(&v);
    return __half22float2(h);
}
__device__ __forceinline__ u32 prmt(u32 v,u32 sel){u32 r;asm("prmt.b32 %0,%1,%1,%2;":"=r"(r):"r"(v),"r"(sel));return r;}
__device__ __forceinline__ void hmma(float* c,u32 a0,u32 a1,u32 a2,u32 a3,u32 b0,u32 b1){
    asm volatile("mma.sync.aligned.m16n8k16.row.col.f32.f16.f16.f32 {%0,%1,%2,%3},{%4,%5,%6,%7},{%8,%9},{%0,%1,%2,%3};"
        : "+f"(c[0]),"+f"(c[1]),"+f"(c[2]),"+f"(c[3])
        : "r"(a0),"r"(a1),"r"(a2),"r"(a3),"r"(b0),"r"(b1));
}
#define LDMX4(r0,r1,r2,r3,addr) \
    asm volatile("ldmatrix.sync.aligned.m8n8.x4.shared.b16 {%0,%1,%2,%3},[%4];" \
        : "=r"(r0),"=r"(r1),"=r"(r2),"=r"(r3) : "r"(addr))

// ---------------- staging ------------------------------------------------------
// mode 0: raw u16 slots (96B/row/chunk)   mode 1: packed trig u32 -> PRMT expand
// mode 2: packed Ax u32 -> E on the fly (uses d cache in smem)
__device__ __forceinline__ void stage_ld(const void* src,int mode,size_t stride,int c,int r,uint4* v){
    if(mode){
        const uint4* s = (const uint4*)((const u32*)src + (size_t)r*stride + c*12);
        v[0]=s[0]; v[1]=s[1]; v[2]=s[2];
    } else {
        const uint4* s = (const uint4*)((const u16*)src + (size_t)r*stride + c*48);
#pragma unroll
        for(int q=0;q<6;++q) v[q]=s[q];
    }
}
__device__ __forceinline__ void stage_st(char* dst,int mode,int perm,const uint4* v,
                                         const float2* dc,int c){
    uint4* d4=(uint4*)dst;
    if(mode==1){
#pragma unroll
        for(int q=0;q<3;++q){
            uint4 pv=v[q], o1, o2;
            o1.x=prmt(pv.x,0x1010u); o1.y=prmt(pv.x,0x3232u);
            o1.z=prmt(pv.y,0x1010u); o1.w=prmt(pv.y,0x3232u);
            o2.x=prmt(pv.z,0x1010u); o2.y=prmt(pv.z,0x3232u);
            o2.z=prmt(pv.w,0x1010u); o2.w=prmt(pv.w,0x3232u);
            d4[2*q]=o1; d4[2*q+1]=o2;
        }
    } else if(mode==2){
#pragma unroll
        for(int q=0;q<3;++q){
            const u32* a = (const u32*)&v[q];
            u32 o[8];
#pragma unroll
            for(int j=0;j<4;++j){
                float2 cs = up16(a[j]);
                float2 dd = dc[c*12 + q*4 + j];
                float er = cs.x*dd.x + cs.y*dd.y;     // conj(Ax)*d (d pre-scaled)
                float ei = cs.x*dd.y - cs.y*dd.x;
                if(perm){ float tp=er; er=ei; ei=-tp; }   // var1: E' = {ei, -er}
                o[2*j]=splitu(er); o[2*j+1]=splitu(ei);
            }
            uint4 o1, o2;
            o1.x=o[0];o1.y=o[1];o1.z=o[2];o1.w=o[3];
            o2.x=o[4];o2.y=o[5];o2.z=o[6];o2.w=o[7];
            d4[2*q]=o1; d4[2*q+1]=o2;
        }
    } else {
#pragma unroll
        for(int q=0;q<6;++q) d4[q]=v[q];
    }
}

// ---------------- GEMM core: M=192, N=192, K-chunk = 48 slots (frozen) --------
__device__ __forceinline__ void compute192(const char* sm,float* acc){
    int lane = threadIdx.x & 31, w = threadIdx.x >> 5;
    int wm = w & 3, wn = w >> 2;
    int q = lane & 7, quad = lane >> 3;
    u32 smu = s2u(sm);
    u32 aAddr0 = smu + (u32)((wm*48 + (quad&1)*8 + q)*112 + ((quad>>1)*8)*2);
    u32 bAddr0 = smu + 21504u + (u32)((wn*64 + ((quad>>1)&1)*8 + q)*112 + ((quad&1)*8)*2);
#pragma unroll
    for(int s=0;s<3;++s){
        u32 a[3][4];
#pragma unroll
        for(int mg=0;mg<3;++mg)
            LDMX4(a[mg][0],a[mg][1],a[mg][2],a[mg][3], aAddr0 + (u32)(mg*16*112 + s*32));
#pragma unroll
        for(int ng=0;ng<4;++ng){
            u32 b0,b1,b2,b3;
            LDMX4(b0,b1,b2,b3, bAddr0 + (u32)(ng*16*112 + s*32));
#pragma unroll
            for(int mg=0;mg<3;++mg){
                hmma(acc + (mg*8 + ng*2    )*4, a[mg][0],a[mg][1],a[mg][2],a[mg][3], b0,b1);
                hmma(acc + (mg*8 + ng*2 + 1)*4, a[mg][0],a[mg][1],a[mg][2],a[mg][3], b2,b3);
            }
        }
    }
}
__device__ __forceinline__ void gemm192(const void* gA,size_t sA,int mA,
                                        const void* gB,size_t sB,int mB,
                                        int perm,int nch,char* sm,const float2* dc,float* acc){
    int t = threadIdx.x;
    int role = t >= 192;
    int r = role ? t-192 : t;
    const void* src = role ? gB : gA;
    int mode = role ? mB : mA;
    size_t stride = role ? sB : sA;
    int prm = role ? 0 : perm;
    char* dst = sm + (role?21504:0) + r*112;
    uint4 v[6];
    stage_ld(src,mode,stride,0,r,v);
    stage_st(dst,mode,prm,v,dc,0);
    __syncthreads();
    for(int c=0;c<nch;++c){
        if(c+1<nch) stage_ld(src,mode,stride,c+1,r,v);
        compute192(sm,acc);
        if(c+1<nch){
            __syncthreads();
            stage_st(dst,mode,prm,v,dc,c+1);
            __syncthreads();
        }
    }
}

// ---------------- builds ----------------
__global__ void k_build_ky(const float* __restrict__ traj){
    int m = blockIdx.x*256 + threadIdx.x;
    int oct = blockIdx.y;
    float ky = traj[2*m+1];
    float ph = ky*(float)(oct*8-96); float r = ph-rintf(ph);
    float s,c; __sincosf(-TWO_PI_F*r,&s,&c);
    float su,cu; __sincosf(-TWO_PI_F*ky,&su,&cu);
    for(int i=0;i<8;++i){
        int y = oct*8+i;
        u32 pk = (u32)h16(c) | ((u32)h16(s)<<16);
        g_opAp[(size_t)m*NPIX + y] = pk;
        g_adjBp[(size_t)y*MPTS + m] = pk;
        float nc = c*cu - s*su; s = s*cu + c*su; c = nc;
    }
}
__global__ void k_build_kx(const float* __restrict__ traj){
    int m = blockIdx.x*256 + threadIdx.x;
    int oct = blockIdx.y;
    float kx = traj[2*m];
    float ph = kx*(float)(oct*8-96); float r = ph-rintf(ph);
    float s,c; __sincosf(-TWO_PI_F*r,&s,&c);
    float su,cu; __sincosf(-TWO_PI_F*kx,&su,&cu);
    for(int i=0;i<8;++i){
        int x = oct*8+i;
        u32 pk = (u32)h16(c) | ((u32)h16(s)<<16);
        g_Am[(size_t)m*NPIX+x]=pk; g_Ax[(size_t)x*MPTS+m]=pk;
        float nc = c*cu - s*su; s = s*cu + c*su; c = nc;
    }
}
__global__ void k_opB(const float* __restrict__ xin){
    int idx = blockIdx.x*256 + threadIdx.x;
    float re = xin[idx], im = xin[NN+idx];
    int x = idx/192, y = idx - x*192;
    u32 rw = splitu(re), iw = splitu(im);
    u32* pr = (u32*)(g_opBr + (size_t)x*KOP + 4*y);
    pr[0]=rw; pr[1]=iw^0x80008000u;
    u32* pi = (u32*)(g_opBi + (size_t)x*KOP + 4*y);
    pi[0]=iw; pi[1]=rw;
}

// ---------------- elementwise ----------------
__global__ void k_winit(){int i=blockIdx.x*256+threadIdx.x;
    g_w[i]=1.0f; g_d[i]=make_float2(ESCALE,0.f);}
__global__ void k_scombw(){int i=blockIdx.x*256+threadIdx.x;
    float sre=g_uv[0][i]-g_uv[3][i], sim=g_uv[2][i]+g_uv[1][i];
    float m=sqrtf(sre*sre+sim*sim);
    float wn=g_w[i]/fmaxf(m,1e-20f);
    g_w[i]=wn; g_d[i]=make_float2(wn*ESCALE,0.f);}
__global__ void k_scombd(){int i=blockIdx.x*256+threadIdx.x;
    float sre=g_uv[0][i]-g_uv[3][i], sim=g_uv[2][i]+g_uv[1][i];
    float wv=g_w[i]*ESCALE;
    g_d[i]=make_float2(wv*sre, wv*sim);}
__global__ void k_reduceB(){
    int idx = blockIdx.x*256 + threadIdx.x;
    float re=0.f, im=0.f;
#pragma unroll 8
    for(int z=0;z<ZS;++z){
        re += g_part[(size_t)z*NN + idx];
        im += g_part[((size_t)(ZS+z))*NN + idx];
    }
    int x = idx/192, y = idx - x*192;
    u32 rw = splitu(re), iw = splitu(im);
    u32* pr = (u32*)(g_opBr + (size_t)x*KOP + 4*y);
    pr[0]=rw; pr[1]=iw^0x80008000u;
    u32* pi = (u32*)(g_opBi + (size_t)x*KOP + 4*y);
    pi[0]=iw; pi[1]=rw;
}
__global__ void k_reduceOut(float* __restrict__ out){
    int idx = blockIdx.x*256 + threadIdx.x;
    int c = idx >= NN;
    int xy = idx - (c?NN:0);
    float s = 0.f;
#pragma unroll 8
    for(int z=0;z<ZS;++z) s += g_part[((size_t)(c*ZS+z))*NN + xy];
    out[idx]=s;
}

// ---------------- op GEMM ------------------------------------------------------
__global__ void __launch_bounds__(384) k_opg(){
    extern __shared__ char dsm[];
    float acc[96];
#pragma unroll
    for(int i=0;i<96;++i) acc[i]=0.f;
    int var = blockIdx.x, blk = blockIdx.y;
    const u32* gA = g_opAp + (size_t)blk*192*NPIX;
    const u16* gB = var ? g_opBi : g_opBr;
    gemm192(gA, NPIX, 1, gB, KOP, 0, 0, 16, dsm, 0, acc);

    int lane = threadIdx.x&31, w = threadIdx.x>>5;
    int wm = w & 3, wn = w >> 2;
    int g = lane>>2, j3 = lane&3;
    float u1[3][2], u2[3][2];
#pragma unroll
    for(int mg=0;mg<3;++mg){ u1[mg][0]=u1[mg][1]=0.f; u2[mg][0]=u2[mg][1]=0.f; }
#pragma unroll
    for(int mg=0;mg<3;++mg){
        int m0 = blk*192 + wm*48 + mg*16 + g;
#pragma unroll
        for(int tp=0;tp<8;++tp){
            int x = wn*64 + tp*8 + 2*j3;
            const float* c = acc + (mg*8+tp)*4;
            u64 w0 = __ldg((const u64*)(g_Am + (size_t)m0*NPIX + x));
            float2 cs0 = up16((u32)w0), cs1 = up16((u32)(w0>>32));
            u1[mg][0] += cs0.x*c[0] + cs1.x*c[1];
            u2[mg][0] += cs0.y*c[0] + cs1.y*c[1];
            u64 w1 = __ldg((const u64*)(g_Am + (size_t)(m0+8)*NPIX + x));
            float2 ds0 = up16((u32)w1), ds1 = up16((u32)(w1>>32));
            u1[mg][1] += ds0.x*c[2] + ds1.x*c[3];
            u2[mg][1] += ds0.y*c[2] + ds1.y*c[3];
        }
    }
#pragma unroll
    for(int o=1;o<4;o<<=1){
#pragma unroll
        for(int mg=0;mg<3;++mg){
            u1[mg][0]+=__shfl_xor_sync(0xffffffffu,u1[mg][0],o);
            u1[mg][1]+=__shfl_xor_sync(0xffffffffu,u1[mg][1],o);
            u2[mg][0]+=__shfl_xor_sync(0xffffffffu,u2[mg][0],o);
            u2[mg][1]+=__shfl_xor_sync(0xffffffffu,u2[mg][1],o);
        }
    }
    __syncthreads();
    float* sr = (float*)dsm;
    if(j3==0){
#pragma unroll
        for(int mg=0;mg<3;++mg){
#pragma unroll
            for(int h=0;h<2;++h){
                int row = h*8 + g;
                int off = (((wn*4 + wm)*3 + mg)*16 + row)*2;
                sr[off]   = u1[mg][h];
                sr[off+1] = u2[mg][h];
            }
        }
    }
    __syncthreads();
    int t = threadIdx.x;
    int row192 = t >> 1, sel = t & 1;
    int twm = row192/48, rem = row192 - twm*48;
    int tmg = rem >> 4, trow = rem & 15;
    float s = 0.f;
#pragma unroll
    for(int qn=0;qn<3;++qn)
        s += sr[(((qn*4 + twm)*3 + tmg)*16 + trow)*2 + sel];
    int m = blk*192 + row192;
    float* dst = sel ? (var ? g_uv[3] : g_uv[1]) : (var ? g_uv[2] : g_uv[0]);
    dst[m] = s;
}

// ---------------- adj GEMM: fused E-build in staging ---------------------------
__global__ void __launch_bounds__(384) k_adjg(){
    extern __shared__ char dsm[];
    int var = blockIdx.x, z = blockIdx.y;
    // stage this z-slice's d (576 float2 = 4608B) into smem
    if(threadIdx.x < 288)
        ((uint4*)(dsm+43008))[threadIdx.x] = ((const uint4*)(g_d + (size_t)z*576))[threadIdx.x];
    __syncthreads();
    float acc[96];
#pragma unroll
    for(int i=0;i<96;++i) acc[i]=0.f;
    const u32* gA = g_Ax + (size_t)z*576;       // packed (c,s), E computed at stage
    const u32* gB = g_adjBp + (size_t)z*576;
    gemm192(gA, MPTS, 2, gB, MPTS, 1, var, 48, dsm, (const float2*)(dsm+43008), acc);

    int lane = threadIdx.x&31, w = threadIdx.x>>5;
    int wm = w & 3, wn = w >> 2;
    int g = lane>>2, j3 = lane&3;
    float* pp = g_part + ((size_t)var*ZS + z)*NN;
#pragma unroll
    for(int mg=0;mg<3;++mg){
        int x0 = wm*48 + mg*16 + g;
#pragma unroll
        for(int tp=0;tp<8;++tp){
            int y = wn*64 + tp*8 + 2*j3;
            const float* c = acc + (mg*8+tp)*4;
            *(float2*)&pp[(size_t)x0*192+y]     = make_float2(c[0]*EUNSC,c[1]*EUNSC);
            *(float2*)&pp[(size_t)(x0+8)*192+y] = make_float2(c[2]*EUNSC,c[3]*EUNSC);
        }
    }
}

// ---------------- driver ----------------
extern "C" void kernel_launch(void* const* d_in, const int* in_sizes, int n_in,
                              void* d_out, int out_size) {
    const float* xin  = (const float*)d_in[0];
    const float* traj = (const float*)d_in[1];
    float* out = (float*)d_out;
    const int SMEM_OP  = 43008;
    const int SMEM_ADJ = 47616;     // + 4608B d-cache, still < 48KB

    dim3 gb(144,24);
    k_build_ky<<<gb,256>>>(traj);
    k_build_kx<<<gb,256>>>(traj);
    k_winit<<<144,256>>>();

    for(int it=0; it<3; ++it){
        k_adjg<<<dim3(2,ZS),384,SMEM_ADJ>>>();
        k_reduceB<<<144,256>>>();
        k_opg<<<dim3(2,192),384,SMEM_OP>>>();
        k_scombw<<<144,256>>>();
    }
    k_opB<<<144,256>>>(xin);
    k_opg<<<dim3(2,192),384,SMEM_OP>>>();
    k_scombd<<<144,256>>>();
    k_adjg<<<dim3(2,ZS),384,SMEM_ADJ>>>();
    k_reduceOut<<<288,256>>>(out);
}